// round 1
// baseline (speedup 1.0000x reference)
#include <cuda_runtime.h>
#include <stdint.h>

// Problem constants (FaceDetector: 1280x1280, strides 8/16/32)
#define BATCH   8
#define NPRIOR  33600           // 160^2 + 80^2 + 40^2
#define TOPK    5000
#define KEEPK   750
#define SORTM   8192            // bitonic pad of TOPK
#define CONF_TH 0.3f
#define NMS_TH  0.3f
#define KMAX    784             // kept-list capacity: 749 + 32 + pad

// ---------------- device scratch (no allocations allowed) ----------------
__device__ unsigned long long g_keys[BATCH * NPRIOR];
__device__ unsigned long long g_top [BATCH * TOPK];
__device__ float4             g_boxes[BATCH * TOPK];
__device__ int                g_fidx [BATCH * KEEPK];
__device__ int                g_outvalid[BATCH * KEEPK];

// ---------------- helpers ----------------
__device__ __forceinline__ unsigned key_from_float(float f) {
    unsigned u = __float_as_uint(f);
    return (u & 0x80000000u) ? ~u : (u | 0x80000000u);   // monotone map
}
__device__ __forceinline__ float float_from_key(unsigned u) {
    return __uint_as_float((u & 0x80000000u) ? (u ^ 0x80000000u) : ~u);
}
__device__ __forceinline__ float iou_f(float4 a, float aa, float4 b, float ab) {
    float lx = fmaxf(a.x, b.x), ly = fmaxf(a.y, b.y);
    float rx = fminf(a.z, b.z), ry = fminf(a.w, b.w);
    float wx = fmaxf(rx - lx, 0.0f), wy = fmaxf(ry - ly, 0.0f);
    float inter = wx * wy;
    return inter / (aa + ab - inter + 1e-12f);
}

// ---------------- K1: scores -> sortable unique keys ----------------
__global__ void k1_keys(const float* __restrict__ cls, const float* __restrict__ obj) {
    int t = blockIdx.x * blockDim.x + threadIdx.x;
    if (t >= BATCH * NPRIOR) return;
    int i = t % NPRIOR;
    float s = sqrtf(cls[t] * obj[t]);
    float m = (s > CONF_TH) ? s : -1.0f;
    unsigned hk = key_from_float(m);
    // high 32: score order; low 32: ~idx -> lower index sorts first on ties
    g_keys[t] = ((unsigned long long)hk << 32) | (unsigned)(~(unsigned)i);
}

// ---------------- K2: per-batch exact top-5000 (radix select + bitonic sort) ----------------
extern __shared__ unsigned long long sh_sort[];   // SORTM u64 = 64KB dynamic

__global__ __launch_bounds__(1024, 1)
void k2_select(const float* __restrict__ bbox, const float* __restrict__ priors) {
    __shared__ unsigned hist[256];
    __shared__ unsigned long long sh_pref;
    __shared__ int sh_k;
    __shared__ int sh_cnt;

    const int b = blockIdx.x, tid = threadIdx.x, nt = blockDim.x;
    const unsigned long long* keys = g_keys + (size_t)b * NPRIOR;

    // --- MSB radix select: find exact 5000th-largest (unique) key ---
    unsigned long long prefix = 0ull;
    int k = TOPK;
    for (int level = 0; level < 8; level++) {
        int shift = 56 - 8 * level;
        for (int d = tid; d < 256; d += nt) hist[d] = 0u;
        __syncthreads();
        for (int i = tid; i < NPRIOR; i += nt) {
            unsigned long long key = keys[i];
            bool match = (level == 0) || ((key >> (shift + 8)) == prefix);
            if (match) atomicAdd(&hist[(unsigned)((key >> shift) & 0xFFull)], 1u);
        }
        __syncthreads();
        if (tid == 0) {
            int cum = 0, dsel = 0;
            for (int d = 255; d >= 0; d--) {
                int c = (int)hist[d];
                if (cum + c >= k) { dsel = d; break; }
                cum += c;
            }
            sh_k = k - cum;
            sh_pref = (prefix << 8) | (unsigned long long)dsel;
        }
        __syncthreads();
        prefix = sh_pref;
        k = sh_k;
        __syncthreads();
    }
    const unsigned long long T = prefix;  // exact 5000th-largest key

    // --- compact selected keys (exactly TOPK of them) into shared ---
    if (tid == 0) sh_cnt = 0;
    for (int i = tid; i < SORTM; i += nt) sh_sort[i] = 0ull;
    __syncthreads();
    for (int i = tid; i < NPRIOR; i += nt) {
        unsigned long long key = keys[i];
        if (key >= T) {
            int p = atomicAdd(&sh_cnt, 1);
            if (p < SORTM) sh_sort[p] = key;
        }
    }
    __syncthreads();

    // --- bitonic sort descending (pad zeros sort last) ---
    for (int kk = 2; kk <= SORTM; kk <<= 1) {
        for (int j = kk >> 1; j > 0; j >>= 1) {
            for (int i = tid; i < SORTM; i += nt) {
                int ixj = i ^ j;
                if (ixj > i) {
                    unsigned long long a = sh_sort[i], c = sh_sort[ixj];
                    bool desc = ((i & kk) == 0);
                    bool sw = desc ? (a < c) : (a > c);
                    if (sw) { sh_sort[i] = c; sh_sort[ixj] = a; }
                }
            }
            __syncthreads();
        }
    }

    // --- emit sorted keys + decode boxes for NMS ---
    for (int r = tid; r < TOPK; r += nt) {
        unsigned long long key = sh_sort[r];
        g_top[(size_t)b * TOPK + r] = key;
        unsigned idx = ~(unsigned)key;
        float px = priors[idx * 4 + 0], py = priors[idx * 4 + 1];
        float pw = priors[idx * 4 + 2], ph = priors[idx * 4 + 3];
        const float* bb = bbox + ((size_t)b * NPRIOR + idx) * 4;
        float cx = px + bb[0] * pw;
        float cy = py + bb[1] * ph;
        float w  = pw * expf(bb[2]);
        float h  = ph * expf(bb[3]);
        float x1 = cx - w * 0.5f, y1 = cy - h * 0.5f;
        g_boxes[(size_t)b * TOPK + r] = make_float4(x1, y1, x1 + w, y1 + h);
    }
}

// ---------------- K3: greedy NMS with 750-kept early exit ----------------
__global__ __launch_bounds__(1024, 1)
void k3_nms() {
    const int b = blockIdx.x;
    __shared__ float4 kbox[KMAX];
    __shared__ float  karea[KMAX];
    __shared__ unsigned short keptpos[KMAX];
    __shared__ unsigned char keepf[TOPK];
    __shared__ float4 cbox[32];
    __shared__ float  carea[32];
    __shared__ int    cvalid[32];
    __shared__ int    csup[32];
    __shared__ int    keptCount;

    const int tid = threadIdx.x, nt = blockDim.x;
    const int warp = tid >> 5, lane = tid & 31;

    for (int i = tid; i < TOPK; i += nt) keepf[i] = 0;
    if (tid == 0) keptCount = 0;
    __syncthreads();

    for (int base = 0; base < TOPK; base += 32) {
        // stage chunk boxes
        if (tid < 32) {
            int p = base + tid;
            float4 bx = make_float4(0.f, 0.f, 0.f, 0.f);
            float sc = -1.0f;
            if (p < TOPK) {
                bx = g_boxes[(size_t)b * TOPK + p];
                sc = float_from_key((unsigned)(g_top[(size_t)b * TOPK + p] >> 32));
            }
            cbox[tid] = bx;
            carea[tid] = fmaxf(bx.z - bx.x, 0.f) * fmaxf(bx.w - bx.y, 0.f);
            cvalid[tid] = (sc > CONF_TH) ? 1 : 0;
        }
        __syncthreads();

        // each warp: is its candidate suppressed by the existing kept set?
        {
            float4 bj = cbox[warp];
            float  aj = carea[warp];
            bool sup = false;
            int kc = keptCount;
            for (int m = lane; m < kc; m += 32) {
                if (iou_f(kbox[m], karea[m], bj, aj) > NMS_TH) { sup = true; break; }
            }
            sup = __any_sync(0xffffffffu, sup);
            if (lane == 0) csup[warp] = sup ? 1 : 0;
        }
        __syncthreads();

        // warp 0: sequential intra-chunk resolution + append kept
        if (warp == 0) {
            int p = base + lane;
            float4 bl = cbox[lane];
            float  al = carea[lane];
            unsigned ov = 0;
            for (int i2 = 0; i2 < lane; i2++)
                if (iou_f(cbox[i2], carea[i2], bl, al) > NMS_TH) ov |= (1u << i2);
            int stat = (cvalid[lane] && !csup[lane]) ? 1 : 0;
            unsigned keepmask = 0;
            for (int i2 = 0; i2 < 32; i2++) {
                unsigned ovi = __shfl_sync(0xffffffffu, ov, i2);
                int      sti = __shfl_sync(0xffffffffu, stat, i2);
                bool ki = sti && ((ovi & keepmask) == 0);
                keepmask |= (ki ? 1u : 0u) << i2;
            }
            bool mykeep = (keepmask >> lane) & 1u;
            if (p < TOPK) keepf[p] = mykeep ? 1 : 0;
            int off = __popc(keepmask & ((1u << lane) - 1u));
            int base0 = keptCount;
            if (mykeep) {
                int dst = base0 + off;
                if (dst < KMAX) { kbox[dst] = bl; karea[dst] = al; keptpos[dst] = (unsigned short)p; }
            }
            if (lane == 0) keptCount = base0 + __popc(keepmask);
        }
        __syncthreads();
        if (keptCount >= KEEPK) break;   // later entries cannot appear in output
    }
    __syncthreads();

    int kc = keptCount;
    int kout = kc < KEEPK ? kc : KEEPK;
    for (int r = tid; r < kout; r += nt) {
        g_fidx[b * KEEPK + r] = keptpos[r];
        g_outvalid[b * KEEPK + r] = 1;
    }
    if (kc < KEEPK && tid == 0) {
        // filler: earliest not-kept positions (jax top_k -1 tie-break = lowest index)
        int w = kc;
        for (int p = 0; p < TOPK && w < KEEPK; p++) {
            if (!keepf[p]) { g_fidx[b * KEEPK + w] = p; g_outvalid[b * KEEPK + w] = 0; w++; }
        }
    }
}

// ---------------- K4: decode + write final 8x750x15 dets (+ valid) ----------------
__global__ void k4_out(const float* __restrict__ bbox, const float* __restrict__ kps,
                       const float* __restrict__ priors, float* __restrict__ out,
                       int write_valid) {
    int t = blockIdx.x * blockDim.x + threadIdx.x;
    if (t >= BATCH * KEEPK) return;
    int b = t / KEEPK;
    int pos = g_fidx[t];
    unsigned long long key = g_top[(size_t)b * TOPK + pos];
    unsigned idx = ~(unsigned)key;
    float score = float_from_key((unsigned)(key >> 32));

    float px = priors[idx * 4 + 0], py = priors[idx * 4 + 1];
    float pw = priors[idx * 4 + 2], ph = priors[idx * 4 + 3];
    const float* bb = bbox + ((size_t)b * NPRIOR + idx) * 4;
    float cx = px + bb[0] * pw, cy = py + bb[1] * ph;
    float w = pw * expf(bb[2]), h = ph * expf(bb[3]);
    float x1 = cx - w * 0.5f, y1 = cy - h * 0.5f;

    float* o = out + (size_t)t * 15;
    o[0] = x1; o[1] = y1; o[2] = x1 + w; o[3] = y1 + h;
    const float* kp = kps + ((size_t)b * NPRIOR + idx) * 10;
#pragma unroll
    for (int m = 0; m < 5; m++) {
        o[4 + 2 * m] = px + kp[2 * m] * pw;
        o[5 + 2 * m] = py + kp[2 * m + 1] * ph;
    }
    o[14] = score;
    if (write_valid)
        out[(size_t)BATCH * KEEPK * 15 + t] = g_outvalid[t] ? 1.0f : 0.0f;
}

// ---------------- launch ----------------
extern "C" void kernel_launch(void* const* d_in, const int* in_sizes, int n_in,
                              void* d_out, int out_size) {
    const float* cls    = (const float*)d_in[0];
    const float* obj    = (const float*)d_in[1];
    const float* bbox   = (const float*)d_in[2];
    const float* kps    = (const float*)d_in[3];
    const float* priors = (const float*)d_in[4];
    float* out = (float*)d_out;

    static int attr_set = 0;
    if (!attr_set) {
        cudaFuncSetAttribute(k2_select, cudaFuncAttributeMaxDynamicSharedMemorySize,
                             SORTM * (int)sizeof(unsigned long long));
        attr_set = 1;
    }

    k1_keys<<<(BATCH * NPRIOR + 255) / 256, 256>>>(cls, obj);
    k2_select<<<BATCH, 1024, SORTM * sizeof(unsigned long long)>>>(bbox, priors);
    k3_nms<<<BATCH, 1024>>>();

    int write_valid = (out_size >= BATCH * KEEPK * 16) ? 1 : 0;
    k4_out<<<(BATCH * KEEPK + 255) / 256, 256>>>(bbox, kps, priors, out, write_valid);
}

// round 2
// speedup vs baseline: 1.5374x; 1.5374x over previous
#include <cuda_runtime.h>
#include <stdint.h>

#define BATCH   8
#define NPRIOR  33600
#define TOPK    5000
#define KEEPK   750
#define CONF_TH 0.3f
#define NMS_TH  0.3f
#define KMAX    784
#define NB      4096
#define CANDCAP 36864
#define BINSCALE (4094.0f / 0.7f)

// ---------------- device scratch ----------------
__device__ unsigned long long g_keys[BATCH * NPRIOR];
__device__ int                g_hist[BATCH * NB];
__device__ int                g_bincur[BATCH * NB];
__device__ int                g_suf[BATCH * (NB + 1)];
__device__ int                g_cb[BATCH];
__device__ int                g_ctot[BATCH];
__device__ unsigned long long g_cand[(size_t)BATCH * CANDCAP];
__device__ unsigned long long g_top [BATCH * TOPK];
__device__ float4             g_boxes[BATCH * TOPK];
__device__ int                g_fidx [BATCH * KEEPK];
__device__ int                g_outvalid[BATCH * KEEPK];

// ---------------- helpers ----------------
__device__ __forceinline__ unsigned key_from_float(float f) {
    unsigned u = __float_as_uint(f);
    return (u & 0x80000000u) ? ~u : (u | 0x80000000u);
}
__device__ __forceinline__ float float_from_key(unsigned u) {
    return __uint_as_float((u & 0x80000000u) ? (u ^ 0x80000000u) : ~u);
}
__device__ __forceinline__ int bin_of(float m) {
    if (!(m > CONF_TH)) return 0;
    int b = (int)((m - CONF_TH) * BINSCALE);
    if (b > 4094) b = 4094;
    return 1 + b;
}
__device__ __forceinline__ float iou_f(float4 a, float aa, float4 b, float ab) {
    float lx = fmaxf(a.x, b.x), ly = fmaxf(a.y, b.y);
    float rx = fminf(a.z, b.z), ry = fminf(a.w, b.w);
    float wx = fmaxf(rx - lx, 0.0f), wy = fmaxf(ry - ly, 0.0f);
    float inter = wx * wy;
    return inter / (aa + ab - inter + 1e-12f);
}

// ---------------- K0: zero histograms ----------------
__global__ void k0_zero() {
    int t = blockIdx.x * blockDim.x + threadIdx.x;
    if (t < BATCH * NB) g_hist[t] = 0;
}

// ---------------- K1: keys + histogram ----------------
__global__ void k1_keys(const float* __restrict__ cls, const float* __restrict__ obj) {
    int t = blockIdx.x * blockDim.x + threadIdx.x;
    if (t >= BATCH * NPRIOR) return;
    int b = t / NPRIOR;
    int i = t - b * NPRIOR;
    float s = sqrtf(cls[t] * obj[t]);
    float m = (s > CONF_TH) ? s : -1.0f;
    unsigned hk = key_from_float(m);
    g_keys[t] = ((unsigned long long)hk << 32) | (unsigned)(~(unsigned)i);
    if (m > CONF_TH) {
        int bin = bin_of(m);
        atomicAdd(&g_hist[b * NB + bin], 1);   // bin-0 (masked) derived, not counted
    }
}

// ---------------- K1b: suffix scan, cutoff bin, offsets ----------------
__global__ __launch_bounds__(1024, 1) void k1b_scan() {
    const int b = blockIdx.x, tid = threadIdx.x;
    const int lane = tid & 31, wid = tid >> 5;
    __shared__ int suf[NB];
    __shared__ int wsum[32];
    __shared__ int sh_cb;

    int rbase = tid * 4;
    int v[4];
#pragma unroll
    for (int j = 0; j < 4; j++) v[j] = g_hist[b * NB + (NB - 1 - (rbase + j))];
    v[1] += v[0]; v[2] += v[1]; v[3] += v[2];
    int tot = v[3];
#pragma unroll
    for (int o = 1; o < 32; o <<= 1) {
        int n = __shfl_up_sync(0xffffffffu, tot, o);
        if (lane >= o) tot += n;
    }
    if (lane == 31) wsum[wid] = tot;
    __syncthreads();
    if (wid == 0) {
        int w = wsum[lane];
#pragma unroll
        for (int o = 1; o < 32; o <<= 1) {
            int n = __shfl_up_sync(0xffffffffu, w, o);
            if (lane >= o) w += n;
        }
        wsum[lane] = w;
    }
    __syncthreads();
    int pre = (wid ? wsum[wid - 1] : 0) + (tot - v[3]);
#pragma unroll
    for (int j = 0; j < 4; j++) suf[NB - 1 - (rbase + j)] = pre + v[j];
    __syncthreads();
    if (tid == 0) { suf[0] = NPRIOR; sh_cb = 0; }   // bin 0 = masked remainder
    __syncthreads();
    int local = -1;
#pragma unroll
    for (int j = 0; j < 4; j++) {
        int bin = NB - 1 - (rbase + j);
        if (suf[bin] >= TOPK && bin > local) local = bin;
    }
    if (local >= 0) atomicMax(&sh_cb, local);
    __syncthreads();
    int cb = sh_cb;
    if (tid == 0) {
        g_cb[b] = cb;
        int ct = suf[cb];
        g_ctot[b] = ct < CANDCAP ? ct : CANDCAP;
        g_suf[b * (NB + 1) + NB] = 0;
    }
    for (int i = tid; i < NB; i += 1024) {
        g_suf[b * (NB + 1) + i] = suf[i];
        g_bincur[b * NB + i] = 0;
    }
}

// ---------------- K2: compact candidates grouped by descending bin ----------------
__global__ void k2_compact() {
    int t = blockIdx.x * blockDim.x + threadIdx.x;
    if (t >= BATCH * NPRIOR) return;
    int b = t / NPRIOR;
    unsigned long long key = g_keys[t];
    float m = float_from_key((unsigned)(key >> 32));
    int bin = bin_of(m);
    if (bin < g_cb[b]) return;
    int pos = g_suf[b * (NB + 1) + bin + 1] + atomicAdd(&g_bincur[b * NB + bin], 1);
    if (pos < CANDCAP) g_cand[(size_t)b * CANDCAP + pos] = key;
}

// ---------------- K3: exact rank within tiny bin segment + decode ----------------
__global__ void k3_rank(const float* __restrict__ bbox, const float* __restrict__ priors) {
    int t = blockIdx.x * blockDim.x + threadIdx.x;
    int b = t / CANDCAP;
    if (b >= BATCH) return;
    int s = t - b * CANDCAP;
    int ct = g_ctot[b];
    if (s >= ct) return;
    unsigned long long key = g_cand[(size_t)b * CANDCAP + s];
    float m = float_from_key((unsigned)(key >> 32));
    int bin = bin_of(m);
    int st = g_suf[b * (NB + 1) + bin + 1];
    int en = g_suf[b * (NB + 1) + bin];
    if (en > ct) en = ct;
    int r = st;
    for (int q = st; q < en; q++)
        if (g_cand[(size_t)b * CANDCAP + q] > key) r++;
    if (r >= TOPK) return;
    g_top[(size_t)b * TOPK + r] = key;

    unsigned idx = ~(unsigned)key;
    float px = priors[idx * 4 + 0], py = priors[idx * 4 + 1];
    float pw = priors[idx * 4 + 2], ph = priors[idx * 4 + 3];
    const float* bb = bbox + ((size_t)b * NPRIOR + idx) * 4;
    float cx = px + bb[0] * pw;
    float cy = py + bb[1] * ph;
    float w  = pw * expf(bb[2]);
    float h  = ph * expf(bb[3]);
    float x1 = cx - w * 0.5f, y1 = cy - h * 0.5f;
    g_boxes[(size_t)b * TOPK + r] = make_float4(x1, y1, x1 + w, y1 + h);
}

// ---------------- K4: greedy NMS with 750-kept early exit ----------------
__global__ __launch_bounds__(1024, 1)
void k4_nms() {
    const int b = blockIdx.x;
    __shared__ float4 kbox[KMAX];
    __shared__ float  karea[KMAX];
    __shared__ unsigned short keptpos[KMAX];
    __shared__ unsigned char keepf[TOPK];
    __shared__ float4 cbox[32];
    __shared__ float  carea[32];
    __shared__ int    cvalid[32];
    __shared__ int    csup[32];
    __shared__ int    keptCount;

    const int tid = threadIdx.x, nt = blockDim.x;
    const int warp = tid >> 5, lane = tid & 31;

    for (int i = tid; i < TOPK; i += nt) keepf[i] = 0;
    if (tid == 0) keptCount = 0;
    __syncthreads();

    for (int base = 0; base < TOPK; base += 32) {
        if (tid < 32) {
            int p = base + tid;
            float4 bx = make_float4(0.f, 0.f, 0.f, 0.f);
            float sc = -1.0f;
            if (p < TOPK) {
                bx = g_boxes[(size_t)b * TOPK + p];
                sc = float_from_key((unsigned)(g_top[(size_t)b * TOPK + p] >> 32));
            }
            cbox[tid] = bx;
            carea[tid] = fmaxf(bx.z - bx.x, 0.f) * fmaxf(bx.w - bx.y, 0.f);
            cvalid[tid] = (sc > CONF_TH) ? 1 : 0;
        }
        __syncthreads();

        {
            float4 bj = cbox[warp];
            float  aj = carea[warp];
            bool sup = false;
            int kc = keptCount;
            for (int m = lane; m < kc; m += 32) {
                if (iou_f(kbox[m], karea[m], bj, aj) > NMS_TH) { sup = true; break; }
            }
            sup = __any_sync(0xffffffffu, sup);
            if (lane == 0) csup[warp] = sup ? 1 : 0;
        }
        __syncthreads();

        if (warp == 0) {
            int p = base + lane;
            float4 bl = cbox[lane];
            float  al = carea[lane];
            unsigned ov = 0;
            for (int i2 = 0; i2 < lane; i2++)
                if (iou_f(cbox[i2], carea[i2], bl, al) > NMS_TH) ov |= (1u << i2);
            int stat = (cvalid[lane] && !csup[lane]) ? 1 : 0;
            unsigned keepmask = 0;
            for (int i2 = 0; i2 < 32; i2++) {
                unsigned ovi = __shfl_sync(0xffffffffu, ov, i2);
                int      sti = __shfl_sync(0xffffffffu, stat, i2);
                bool ki = sti && ((ovi & keepmask) == 0);
                keepmask |= (ki ? 1u : 0u) << i2;
            }
            bool mykeep = (keepmask >> lane) & 1u;
            if (p < TOPK) keepf[p] = mykeep ? 1 : 0;
            int off = __popc(keepmask & ((1u << lane) - 1u));
            int base0 = keptCount;
            if (mykeep) {
                int dst = base0 + off;
                if (dst < KMAX) { kbox[dst] = bl; karea[dst] = al; keptpos[dst] = (unsigned short)p; }
            }
            if (lane == 0) keptCount = base0 + __popc(keepmask);
        }
        __syncthreads();
        if (keptCount >= KEEPK) break;
    }
    __syncthreads();

    int kc = keptCount;
    int kout = kc < KEEPK ? kc : KEEPK;
    for (int r = tid; r < kout; r += nt) {
        g_fidx[b * KEEPK + r] = keptpos[r];
        g_outvalid[b * KEEPK + r] = 1;
    }
    if (kc < KEEPK && tid == 0) {
        int w = kc;
        for (int p = 0; p < TOPK && w < KEEPK; p++) {
            if (!keepf[p]) { g_fidx[b * KEEPK + w] = p; g_outvalid[b * KEEPK + w] = 0; w++; }
        }
    }
}

// ---------------- K5: final dets ----------------
__global__ void k5_out(const float* __restrict__ bbox, const float* __restrict__ kps,
                       const float* __restrict__ priors, float* __restrict__ out,
                       int write_valid) {
    int t = blockIdx.x * blockDim.x + threadIdx.x;
    if (t >= BATCH * KEEPK) return;
    int b = t / KEEPK;
    int pos = g_fidx[t];
    unsigned long long key = g_top[(size_t)b * TOPK + pos];
    unsigned idx = ~(unsigned)key;
    float score = float_from_key((unsigned)(key >> 32));

    float px = priors[idx * 4 + 0], py = priors[idx * 4 + 1];
    float pw = priors[idx * 4 + 2], ph = priors[idx * 4 + 3];
    const float* bb = bbox + ((size_t)b * NPRIOR + idx) * 4;
    float cx = px + bb[0] * pw, cy = py + bb[1] * ph;
    float w = pw * expf(bb[2]), h = ph * expf(bb[3]);
    float x1 = cx - w * 0.5f, y1 = cy - h * 0.5f;

    float* o = out + (size_t)t * 15;
    o[0] = x1; o[1] = y1; o[2] = x1 + w; o[3] = y1 + h;
    const float* kp = kps + ((size_t)b * NPRIOR + idx) * 10;
#pragma unroll
    for (int m = 0; m < 5; m++) {
        o[4 + 2 * m] = px + kp[2 * m] * pw;
        o[5 + 2 * m] = py + kp[2 * m + 1] * ph;
    }
    o[14] = score;
    if (write_valid)
        out[(size_t)BATCH * KEEPK * 15 + t] = g_outvalid[t] ? 1.0f : 0.0f;
}

// ---------------- launch ----------------
extern "C" void kernel_launch(void* const* d_in, const int* in_sizes, int n_in,
                              void* d_out, int out_size) {
    const float* cls    = (const float*)d_in[0];
    const float* obj    = (const float*)d_in[1];
    const float* bbox   = (const float*)d_in[2];
    const float* kps    = (const float*)d_in[3];
    const float* priors = (const float*)d_in[4];
    float* out = (float*)d_out;

    k0_zero<<<(BATCH * NB + 255) / 256, 256>>>();
    k1_keys<<<(BATCH * NPRIOR + 255) / 256, 256>>>(cls, obj);
    k1b_scan<<<BATCH, 1024>>>();
    k2_compact<<<(BATCH * NPRIOR + 255) / 256, 256>>>();
    k3_rank<<<(BATCH * CANDCAP + 255) / 256, 256>>>(bbox, priors);
    k4_nms<<<BATCH, 1024>>>();

    int write_valid = (out_size >= BATCH * KEEPK * 16) ? 1 : 0;
    k5_out<<<(BATCH * KEEPK + 255) / 256, 256>>>(bbox, kps, priors, out, write_valid);
}

// round 3
// speedup vs baseline: 2.2469x; 1.4615x over previous
#include <cuda_runtime.h>
#include <stdint.h>

#define BATCH   8
#define NPRIOR  33600
#define TOPK    5000
#define KEEPK   750
#define CONF_TH 0.3f
#define NMS_TH  0.3f
#define NB      4096
#define CANDS   6144
#define KMAX    784
#define BINSCALE (4094.0f / 0.7f)
#define KEYTH   0xBE99999Au     // key_from_float(0.3f)

typedef unsigned long long ull;

// ---- dynamic shared layout (bytes) ----
#define OFF_SBOX  0                       // float4[5000]  = 80000
#define OFF_SKEY  80000                   // ull[5000]     = 40000
#define OFF_CAND  120000                  // ull[6144]     = 49152  (overlaid by NMS arrays)
#define OFF_KBOX  120000                  //   float4[784] = 12544
#define OFF_KAREA 132544                  //   float[784]  = 3136
#define OFF_KPOS  135680                  //   u16[784]    = 1568
#define OFF_KEEPF 137248                  //   u8[5000]    = 5000
#define OFF_SUF   169152                  // int[4097]     = 16388
#define OFF_HIST  185540                  // int[4096]     = 16384
#define SMEM_TOTAL 201924

__device__ __forceinline__ unsigned key_from_float(float f) {
    unsigned u = __float_as_uint(f);
    return (u & 0x80000000u) ? ~u : (u | 0x80000000u);
}
__device__ __forceinline__ float float_from_key(unsigned u) {
    return __uint_as_float((u & 0x80000000u) ? (u ^ 0x80000000u) : ~u);
}
__device__ __forceinline__ int bin_of(float m) {
    if (!(m > CONF_TH)) return 0;
    int b = (int)((m - CONF_TH) * BINSCALE);
    if (b > 4094) b = 4094;
    return 1 + b;
}
__device__ __forceinline__ float iou_f(float4 a, float aa, float4 b, float ab) {
    float lx = fmaxf(a.x, b.x), ly = fmaxf(a.y, b.y);
    float rx = fminf(a.z, b.z), ry = fminf(a.w, b.w);
    float wx = fmaxf(rx - lx, 0.0f), wy = fmaxf(ry - ly, 0.0f);
    float inter = wx * wy;
    return inter / (aa + ab - inter + 1e-12f);
}
// priors computed arithmetically (exact: small ints scaled by stride)
__device__ __forceinline__ void prior_of(unsigned idx, float& px, float& py, float& ps) {
    if (idx < 25600u)      { ps = 8.0f;  px = (float)((idx % 160u) * 8u);            py = (float)((idx / 160u) * 8u); }
    else if (idx < 32000u) { unsigned j = idx - 25600u; ps = 16.0f; px = (float)((j % 80u) * 16u); py = (float)((j / 80u) * 16u); }
    else                   { unsigned j = idx - 32000u; ps = 32.0f; px = (float)((j % 40u) * 32u); py = (float)((j / 40u) * 32u); }
}

extern __shared__ char smem[];

__global__ __launch_bounds__(1024, 1)
void fused_detector(const float* __restrict__ cls, const float* __restrict__ obj,
                    const float* __restrict__ bbox, const float* __restrict__ kps,
                    float* __restrict__ out, int write_valid) {
    float4* sbox = (float4*)(smem + OFF_SBOX);
    ull*    skey = (ull*)   (smem + OFF_SKEY);
    ull*    cand = (ull*)   (smem + OFF_CAND);
    float4* kbox = (float4*)(smem + OFF_KBOX);
    float*  karea= (float*) (smem + OFF_KAREA);
    unsigned short* kpos = (unsigned short*)(smem + OFF_KPOS);
    unsigned char*  keepf= (unsigned char*) (smem + OFF_KEEPF);
    int*    suf  = (int*)   (smem + OFF_SUF);
    int*    hist = (int*)   (smem + OFF_HIST);

    __shared__ int wsum[32];
    __shared__ int sh_cb;
    __shared__ unsigned ovArr[32];
    __shared__ int statArr[32];
    __shared__ int keptCount;

    const int b = blockIdx.x, tid = threadIdx.x;
    const int lane = tid & 31, warp = tid >> 5;
    const size_t boff = (size_t)b * NPRIOR;

    // ---- P1: zero histogram + skey ----
    for (int i = tid; i < NB; i += 1024) hist[i] = 0;
    for (int i = tid; i < TOPK; i += 1024) skey[i] = 0ull;
    if (tid == 0) { sh_cb = 0; keptCount = 0; }
    __syncthreads();

    // ---- P2: histogram of masked scores ----
    for (int i = tid; i < NPRIOR; i += 1024) {
        float s = sqrtf(cls[boff + i] * obj[boff + i]);
        if (s > CONF_TH) atomicAdd(&hist[bin_of(s)], 1);
    }
    __syncthreads();

    // ---- P3: suffix scan over bins (high->low), find cutoff bin ----
    {
        int rbase = tid * 4;
        int v[4];
#pragma unroll
        for (int j = 0; j < 4; j++) v[j] = hist[NB - 1 - (rbase + j)];
        v[1] += v[0]; v[2] += v[1]; v[3] += v[2];
        int tot = v[3];
#pragma unroll
        for (int o = 1; o < 32; o <<= 1) {
            int n = __shfl_up_sync(0xffffffffu, tot, o);
            if (lane >= o) tot += n;
        }
        if (lane == 31) wsum[warp] = tot;
        __syncthreads();
        if (warp == 0) {
            int w = wsum[lane];
#pragma unroll
            for (int o = 1; o < 32; o <<= 1) {
                int n = __shfl_up_sync(0xffffffffu, w, o);
                if (lane >= o) w += n;
            }
            wsum[lane] = w;
        }
        __syncthreads();
        int pre = (warp ? wsum[warp - 1] : 0) + (tot - v[3]);
#pragma unroll
        for (int j = 0; j < 4; j++) suf[NB - 1 - (rbase + j)] = pre + v[j];
        __syncthreads();
        if (tid == 0) { suf[0] = NPRIOR; suf[NB] = 0; }
        __syncthreads();
        int local = -1;
#pragma unroll
        for (int j = 0; j < 4; j++) {
            int bin = NB - 1 - (rbase + j);
            if (bin >= 1 && suf[bin] >= TOPK && bin > local) local = bin;
        }
        if (local >= 0) atomicMax(&sh_cb, local);
        __syncthreads();
    }
    int cb = sh_cb; if (cb < 1) cb = 1;
    int ctot = suf[cb]; if (ctot > CANDS) ctot = CANDS;
    // reuse hist as per-bin running counters
    __syncthreads();
    for (int i = tid; i < NB; i += 1024) hist[i] = 0;
    __syncthreads();

    // ---- P4: compact candidates (grouped by bin) into shared ----
    for (int i = tid; i < NPRIOR; i += 1024) {
        float s = sqrtf(cls[boff + i] * obj[boff + i]);
        float m = (s > CONF_TH) ? s : -1.0f;
        int bin = bin_of(m);
        if (bin < cb) continue;
        int pos = suf[bin + 1] + atomicAdd(&hist[bin], 1);
        if (pos < CANDS) {
            unsigned hk = key_from_float(m);
            cand[pos] = ((ull)hk << 32) | (unsigned)(~(unsigned)i);
        }
    }
    __syncthreads();

    // ---- P5: exact rank within tiny bin segment + decode boxes ----
    for (int s = tid; s < ctot; s += 1024) {
        ull key = cand[s];
        float m = float_from_key((unsigned)(key >> 32));
        int bin = bin_of(m);
        int st = suf[bin + 1];
        int en = suf[bin]; if (en > ctot) en = ctot;
        int r = st;
        for (int q = st; q < en; q++)
            if (cand[q] > key) r++;
        if (r >= TOPK) continue;
        skey[r] = key;
        unsigned idx = ~(unsigned)key;
        float px, py, ps; prior_of(idx, px, py, ps);
        const float* bb = bbox + (boff + idx) * 4;
        float cx = px + bb[0] * ps;
        float cy = py + bb[1] * ps;
        float w  = ps * expf(bb[2]);
        float h  = ps * expf(bb[3]);
        float x1 = cx - w * 0.5f, y1 = cy - h * 0.5f;
        sbox[r] = make_float4(x1, y1, x1 + w, y1 + h);
    }
    __syncthreads();   // cand region now free -> NMS overlays

    // ---- P6: greedy NMS, 32-candidate chunks, early exit at 750 kept ----
    for (int i = tid; i < TOPK; i += 1024) keepf[i] = 0;
    __syncthreads();

    for (int base = 0; base < TOPK; base += 32) {
        // parallel phase: warp w evaluates candidate base+w
        {
            int p = base + warp;
            float4 bj = make_float4(0.f, 0.f, 0.f, 0.f);
            float aj = 0.f; int stat = 0;
            if (p < TOPK) {
                bj = sbox[p];
                aj = fmaxf(bj.z - bj.x, 0.f) * fmaxf(bj.w - bj.y, 0.f);
                stat = ((unsigned)(skey[p] >> 32)) > KEYTH;
            }
            // intra-chunk: does earlier candidate (lane) overlap me?
            bool ob = false;
            if (lane < warp) {
                float4 bi = sbox[base + lane];
                float ai = fmaxf(bi.z - bi.x, 0.f) * fmaxf(bi.w - bi.y, 0.f);
                ob = iou_f(bi, ai, bj, aj) > NMS_TH;
            }
            unsigned ov = __ballot_sync(0xffffffffu, ob);
            // kept-list suppression
            bool sup = false;
            int kc = keptCount;
            for (int m = lane; m < kc; m += 32)
                if (iou_f(kbox[m], karea[m], bj, aj) > NMS_TH) { sup = true; break; }
            sup = __any_sync(0xffffffffu, sup);
            if (lane == 0) { ovArr[warp] = ov; statArr[warp] = (stat && !sup) ? 1 : 0; }
        }
        __syncthreads();

        // resolution phase: warp 0 only
        if (warp == 0) {
            unsigned ov = ovArr[lane];
            unsigned alive = __ballot_sync(0xffffffffu, statArr[lane]);
            unsigned keepmask = 0;
            while (alive) {
                int i = __ffs((int)alive) - 1;
                keepmask |= 1u << i;
                unsigned supby = __ballot_sync(0xffffffffu, (ov >> i) & 1u);
                alive &= ~supby;
                alive &= ~(1u << i);
            }
            int p = base + lane;
            bool mykeep = (keepmask >> lane) & 1u;
            if (p < TOPK) keepf[p] = mykeep ? 1 : 0;
            int off = __popc(keepmask & ((1u << lane) - 1u));
            int b0 = keptCount;
            if (mykeep) {
                int dst = b0 + off;
                float4 bl = sbox[p];
                kbox[dst] = bl;
                karea[dst] = fmaxf(bl.z - bl.x, 0.f) * fmaxf(bl.w - bl.y, 0.f);
                kpos[dst] = (unsigned short)p;
            }
            if (lane == 0) keptCount = b0 + __popc(keepmask);
        }
        __syncthreads();
        if (keptCount >= KEEPK) break;
    }
    __syncthreads();

    int kc = keptCount;
    int kout = kc < KEEPK ? kc : KEEPK;
    if (kc < KEEPK && tid == 0) {
        // filler: earliest not-kept positions (ties at -1 break by lowest index)
        int w = kc;
        for (int p = 0; p < TOPK && w < KEEPK; p++)
            if (!keepf[p]) kpos[w++] = (unsigned short)p;
    }
    __syncthreads();

    // ---- P7: write final 750 rows ----
    for (int r = tid; r < KEEPK; r += 1024) {
        int pos = kpos[r];
        ull key = skey[pos];
        unsigned idx = ~(unsigned)key;
        float score = float_from_key((unsigned)(key >> 32));
        float px, py, ps; prior_of(idx, px, py, ps);
        const float* bb = bbox + (boff + idx) * 4;
        float cx = px + bb[0] * ps, cy = py + bb[1] * ps;
        float w = ps * expf(bb[2]), h = ps * expf(bb[3]);
        float x1 = cx - w * 0.5f, y1 = cy - h * 0.5f;
        size_t t = (size_t)b * KEEPK + r;
        float* o = out + t * 15;
        o[0] = x1; o[1] = y1; o[2] = x1 + w; o[3] = y1 + h;
        const float* kp = kps + (boff + idx) * 10;
#pragma unroll
        for (int m = 0; m < 5; m++) {
            o[4 + 2 * m] = px + kp[2 * m] * ps;
            o[5 + 2 * m] = py + kp[2 * m + 1] * ps;
        }
        o[14] = score;
        if (write_valid)
            out[(size_t)BATCH * KEEPK * 15 + t] = (r < kout) ? 1.0f : 0.0f;
    }
}

extern "C" void kernel_launch(void* const* d_in, const int* in_sizes, int n_in,
                              void* d_out, int out_size) {
    const float* cls  = (const float*)d_in[0];
    const float* obj  = (const float*)d_in[1];
    const float* bbox = (const float*)d_in[2];
    const float* kps  = (const float*)d_in[3];
    float* out = (float*)d_out;

    static int attr_set = 0;
    if (!attr_set) {
        cudaFuncSetAttribute(fused_detector, cudaFuncAttributeMaxDynamicSharedMemorySize,
                             SMEM_TOTAL);
        attr_set = 1;
    }
    int write_valid = (out_size >= BATCH * KEEPK * 16) ? 1 : 0;
    fused_detector<<<BATCH, 1024, SMEM_TOTAL>>>(cls, obj, bbox, kps, out, write_valid);
}

// round 4
// speedup vs baseline: 3.3389x; 1.4861x over previous
#include <cuda_runtime.h>
#include <stdint.h>

#define BATCH   8
#define NPRIOR  33600
#define TOPK    5000
#define KEEPK   750
#define CONF_TH 0.3f
#define NMS_TH  0.3f
#define NB      4096
#define CANDS   6144
#define KMAX    784
#define BINSCALE (4094.0f / 0.7f)
#define KEYTH   0xBE99999Au     // key_from_float(0.3f)

typedef unsigned long long ull;

// ---- dynamic shared layout (bytes) ----
// NOTE: boxes stored as (x1, x2, y1, y2) for the interval-reject fast path.
#define OFF_SBOX  0                       // float4[5000]  = 80000
#define OFF_SKEY  80000                   // ull[5000]     = 40000
#define OFF_CAND  120000                  // ull[6144]     = 49152  (overlaid by NMS arrays)
#define OFF_KBOX  120000                  //   float4[784] = 12544
#define OFF_KAREA 132544                  //   float[784]  = 3136
#define OFF_KPOS  135680                  //   u16[784]    = 1568
#define OFF_KEEPF 137248                  //   u8[5000]    = 5000
#define OFF_SUF   169152                  // int[4097]     = 16388
#define OFF_HIST  185540                  // int[4096]     = 16384
#define SMEM_TOTAL 201924

__device__ __forceinline__ unsigned key_from_float(float f) {
    unsigned u = __float_as_uint(f);
    return (u & 0x80000000u) ? ~u : (u | 0x80000000u);
}
__device__ __forceinline__ float float_from_key(unsigned u) {
    return __uint_as_float((u & 0x80000000u) ? (u ^ 0x80000000u) : ~u);
}
__device__ __forceinline__ int bin_of(float m) {
    if (!(m > CONF_TH)) return 0;
    int b = (int)((m - CONF_TH) * BINSCALE);
    if (b > 4094) b = 4094;
    return 1 + b;
}
// box = (x1, x2, y1, y2). Exact vs reference: overlap fails -> iou <= 0 -> keep;
// overlap holds -> xo*yo == clamped product, identical IEEE division + compare.
__device__ __forceinline__ bool sup_test(float4 a, float aa, float4 b, float ab) {
    float xo = fminf(a.y, b.y) - fmaxf(a.x, b.x);
    float yo = fminf(a.w, b.w) - fmaxf(a.z, b.z);
    if (xo > 0.0f && yo > 0.0f) {
        float inter = xo * yo;
        return inter / (aa + ab - inter + 1e-12f) > NMS_TH;
    }
    return false;
}
// priors computed arithmetically (exact: small ints scaled by stride)
__device__ __forceinline__ void prior_of(unsigned idx, float& px, float& py, float& ps) {
    if (idx < 25600u)      { ps = 8.0f;  px = (float)((idx % 160u) * 8u);            py = (float)((idx / 160u) * 8u); }
    else if (idx < 32000u) { unsigned j = idx - 25600u; ps = 16.0f; px = (float)((j % 80u) * 16u); py = (float)((j / 80u) * 16u); }
    else                   { unsigned j = idx - 32000u; ps = 32.0f; px = (float)((j % 40u) * 32u); py = (float)((j / 40u) * 32u); }
}

extern __shared__ char smem[];

__global__ __launch_bounds__(1024, 1)
void fused_detector(const float* __restrict__ cls, const float* __restrict__ obj,
                    const float* __restrict__ bbox, const float* __restrict__ kps,
                    float* __restrict__ out, int write_valid) {
    float4* sbox = (float4*)(smem + OFF_SBOX);     // (x1,x2,y1,y2)
    ull*    skey = (ull*)   (smem + OFF_SKEY);
    ull*    cand = (ull*)   (smem + OFF_CAND);
    float4* kbox = (float4*)(smem + OFF_KBOX);     // (x1,x2,y1,y2)
    float*  karea= (float*) (smem + OFF_KAREA);
    unsigned short* kpos = (unsigned short*)(smem + OFF_KPOS);
    unsigned char*  keepf= (unsigned char*) (smem + OFF_KEEPF);
    int*    suf  = (int*)   (smem + OFF_SUF);
    int*    hist = (int*)   (smem + OFF_HIST);

    __shared__ int wsum[32];
    __shared__ int sh_cb;
    __shared__ unsigned ovArr[32];
    __shared__ int statArr[32];
    __shared__ int keptCount;

    const int b = blockIdx.x, tid = threadIdx.x;
    const int lane = tid & 31, warp = tid >> 5;
    const size_t boff = (size_t)b * NPRIOR;

    // ---- P1: zero histogram + skey ----
    for (int i = tid; i < NB; i += 1024) hist[i] = 0;
    for (int i = tid; i < TOPK; i += 1024) skey[i] = 0ull;
    if (tid == 0) { sh_cb = 0; keptCount = 0; }
    __syncthreads();

    // ---- P2: histogram of masked scores ----
    for (int i = tid; i < NPRIOR; i += 1024) {
        float s = sqrtf(cls[boff + i] * obj[boff + i]);
        if (s > CONF_TH) atomicAdd(&hist[bin_of(s)], 1);
    }
    __syncthreads();

    // ---- P3: suffix scan over bins (high->low), find cutoff bin ----
    {
        int rbase = tid * 4;
        int v[4];
#pragma unroll
        for (int j = 0; j < 4; j++) v[j] = hist[NB - 1 - (rbase + j)];
        v[1] += v[0]; v[2] += v[1]; v[3] += v[2];
        int tot = v[3];
#pragma unroll
        for (int o = 1; o < 32; o <<= 1) {
            int n = __shfl_up_sync(0xffffffffu, tot, o);
            if (lane >= o) tot += n;
        }
        if (lane == 31) wsum[warp] = tot;
        __syncthreads();
        if (warp == 0) {
            int w = wsum[lane];
#pragma unroll
            for (int o = 1; o < 32; o <<= 1) {
                int n = __shfl_up_sync(0xffffffffu, w, o);
                if (lane >= o) w += n;
            }
            wsum[lane] = w;
        }
        __syncthreads();
        int pre = (warp ? wsum[warp - 1] : 0) + (tot - v[3]);
#pragma unroll
        for (int j = 0; j < 4; j++) suf[NB - 1 - (rbase + j)] = pre + v[j];
        __syncthreads();
        if (tid == 0) { suf[0] = NPRIOR; suf[NB] = 0; }
        __syncthreads();
        int local = -1;
#pragma unroll
        for (int j = 0; j < 4; j++) {
            int bin = NB - 1 - (rbase + j);
            if (bin >= 1 && suf[bin] >= TOPK && bin > local) local = bin;
        }
        if (local >= 0) atomicMax(&sh_cb, local);
        __syncthreads();
    }
    int cb = sh_cb; if (cb < 1) cb = 1;
    int ctot = suf[cb]; if (ctot > CANDS) ctot = CANDS;
    __syncthreads();
    for (int i = tid; i < NB; i += 1024) hist[i] = 0;   // reuse as per-bin counters
    __syncthreads();

    // ---- P4: compact candidates (grouped by bin) into shared ----
    for (int i = tid; i < NPRIOR; i += 1024) {
        float s = sqrtf(cls[boff + i] * obj[boff + i]);
        float m = (s > CONF_TH) ? s : -1.0f;
        int bin = bin_of(m);
        if (bin < cb) continue;
        int pos = suf[bin + 1] + atomicAdd(&hist[bin], 1);
        if (pos < CANDS) {
            unsigned hk = key_from_float(m);
            cand[pos] = ((ull)hk << 32) | (unsigned)(~(unsigned)i);
        }
    }
    __syncthreads();

    // ---- P5: exact rank within tiny bin segment + decode boxes ----
    for (int s = tid; s < ctot; s += 1024) {
        ull key = cand[s];
        float m = float_from_key((unsigned)(key >> 32));
        int bin = bin_of(m);
        int st = suf[bin + 1];
        int en = suf[bin]; if (en > ctot) en = ctot;
        int r = st;
        for (int q = st; q < en; q++)
            if (cand[q] > key) r++;
        if (r >= TOPK) continue;
        skey[r] = key;
        unsigned idx = ~(unsigned)key;
        float px, py, ps; prior_of(idx, px, py, ps);
        const float* bb = bbox + (boff + idx) * 4;
        float cx = px + bb[0] * ps;
        float cy = py + bb[1] * ps;
        float w  = ps * expf(bb[2]);
        float h  = ps * expf(bb[3]);
        float x1 = cx - w * 0.5f, y1 = cy - h * 0.5f;
        sbox[r] = make_float4(x1, x1 + w, y1, y1 + h);   // (x1,x2,y1,y2)
    }
    __syncthreads();   // cand region now free -> NMS overlays

    // ---- P6: greedy NMS, 32-candidate chunks, early exit at 750 kept ----
    for (int i = tid; i < TOPK; i += 1024) keepf[i] = 0;
    __syncthreads();

    for (int base = 0; base < TOPK; base += 32) {
        // parallel phase: warp w evaluates candidate base+w
        {
            int p = base + warp;
            float4 bj = make_float4(0.f, 0.f, 0.f, 0.f);
            float aj = 0.f; int stat = 0;
            if (p < TOPK) {
                bj = sbox[p];
                aj = fmaxf(bj.y - bj.x, 0.f) * fmaxf(bj.w - bj.z, 0.f);
                stat = ((unsigned)(skey[p] >> 32)) > KEYTH;
            }
            // intra-chunk: does earlier candidate (lane) overlap me?
            bool ob = false;
            if (lane < warp) {
                float4 bi = sbox[base + lane];
                float ai = fmaxf(bi.y - bi.x, 0.f) * fmaxf(bi.w - bi.z, 0.f);
                ob = sup_test(bi, ai, bj, aj);
            }
            unsigned ov = __ballot_sync(0xffffffffu, ob);
            // kept-list suppression with interval fast-reject (hot loop)
            bool sup = false;
            int kc = keptCount;
            for (int m = lane; m < kc; m += 32) {
                float4 kb = kbox[m];
                float xo = fminf(kb.y, bj.y) - fmaxf(kb.x, bj.x);
                float yo = fminf(kb.w, bj.w) - fmaxf(kb.z, bj.z);
                if (xo > 0.0f && yo > 0.0f) {
                    float inter = xo * yo;
                    if (inter / (karea[m] + aj - inter + 1e-12f) > NMS_TH) { sup = true; break; }
                }
            }
            sup = __any_sync(0xffffffffu, sup);
            if (lane == 0) { ovArr[warp] = ov; statArr[warp] = (stat && !sup) ? 1 : 0; }
        }
        __syncthreads();

        // resolution phase: warp 0 only
        if (warp == 0) {
            unsigned ov = ovArr[lane];
            unsigned alive = __ballot_sync(0xffffffffu, statArr[lane]);
            unsigned keepmask = 0;
            while (alive) {
                int i = __ffs((int)alive) - 1;
                keepmask |= 1u << i;
                unsigned supby = __ballot_sync(0xffffffffu, (ov >> i) & 1u);
                alive &= ~supby;
                alive &= ~(1u << i);
            }
            int p = base + lane;
            bool mykeep = (keepmask >> lane) & 1u;
            if (p < TOPK) keepf[p] = mykeep ? 1 : 0;
            int off = __popc(keepmask & ((1u << lane) - 1u));
            int b0 = keptCount;
            if (mykeep) {
                int dst = b0 + off;
                float4 bl = sbox[p];
                kbox[dst] = bl;
                karea[dst] = fmaxf(bl.y - bl.x, 0.f) * fmaxf(bl.w - bl.z, 0.f);
                kpos[dst] = (unsigned short)p;
            }
            if (lane == 0) keptCount = b0 + __popc(keepmask);
        }
        __syncthreads();
        if (keptCount >= KEEPK) break;
    }
    __syncthreads();

    int kc = keptCount;
    int kout = kc < KEEPK ? kc : KEEPK;
    if (kc < KEEPK && tid == 0) {
        int w = kc;
        for (int p = 0; p < TOPK && w < KEEPK; p++)
            if (!keepf[p]) kpos[w++] = (unsigned short)p;
    }
    __syncthreads();

    // ---- P7: write final 750 rows ----
    for (int r = tid; r < KEEPK; r += 1024) {
        int pos = kpos[r];
        ull key = skey[pos];
        unsigned idx = ~(unsigned)key;
        float score = float_from_key((unsigned)(key >> 32));
        float px, py, ps; prior_of(idx, px, py, ps);
        const float* bb = bbox + (boff + idx) * 4;
        float cx = px + bb[0] * ps, cy = py + bb[1] * ps;
        float w = ps * expf(bb[2]), h = ps * expf(bb[3]);
        float x1 = cx - w * 0.5f, y1 = cy - h * 0.5f;
        size_t t = (size_t)b * KEEPK + r;
        float* o = out + t * 15;
        o[0] = x1; o[1] = y1; o[2] = x1 + w; o[3] = y1 + h;
        const float* kp = kps + (boff + idx) * 10;
#pragma unroll
        for (int m = 0; m < 5; m++) {
            o[4 + 2 * m] = px + kp[2 * m] * ps;
            o[5 + 2 * m] = py + kp[2 * m + 1] * ps;
        }
        o[14] = score;
        if (write_valid)
            out[(size_t)BATCH * KEEPK * 15 + t] = (r < kout) ? 1.0f : 0.0f;
    }
}

extern "C" void kernel_launch(void* const* d_in, const int* in_sizes, int n_in,
                              void* d_out, int out_size) {
    const float* cls  = (const float*)d_in[0];
    const float* obj  = (const float*)d_in[1];
    const float* bbox = (const float*)d_in[2];
    const float* kps  = (const float*)d_in[3];
    float* out = (float*)d_out;

    static int attr_set = 0;
    if (!attr_set) {
        cudaFuncSetAttribute(fused_detector, cudaFuncAttributeMaxDynamicSharedMemorySize,
                             SMEM_TOTAL);
        attr_set = 1;
    }
    int write_valid = (out_size >= BATCH * KEEPK * 16) ? 1 : 0;
    fused_detector<<<BATCH, 1024, SMEM_TOTAL>>>(cls, obj, bbox, kps, out, write_valid);
}

// round 5
// speedup vs baseline: 4.9331x; 1.4774x over previous
#include <cuda_runtime.h>
#include <stdint.h>

#define BATCH   8
#define NPRIOR  33600
#define TOPK    5000
#define KEEPK   750
#define CONF_TH 0.3f
#define NMS_TH  0.3f
#define NB      4096
#define CANDS   6144
#define BINSCALE (4094.0f / 0.7f)
#define KEYTH   0xBE99999Au     // key_from_float(0.3f)

#define NCOL    20
#define COLCAP  160
#define LARGECAP 256
#define INVCOLW (1.0f / 64.0f)

typedef unsigned long long ull;

// ---- dynamic shared layout (bytes) ----
// prep arrays (cand/suf/hist) are dead after P5; NMS arrays overlay them.
#define OFF_SBOX   0                      // float4[5000] = 80000   (x1,x2,y1,y2)
#define OFF_SKEY   80000                  // ull[5000]    = 40000
#define OFF_CAND   120000                 // ull[6144]    = 49152   (prep)
#define OFF_SUF    169152                 // int[4097]    = 16388   (prep)
#define OFF_HIST   185540                 // int[4096]    = 16384   (prep)
// --- NMS overlay (valid after P5) ---
#define OFF_COLBOX 120000                 // float4[20*160] = 51200
#define OFF_LARGE  171200                 // float4[256]    = 4096
#define OFF_KPOS   175296                 // u16[784]       = 1568
#define OFF_KEEPF  176864                 // u8[5000]       = 5000
#define SMEM_TOTAL 201924

__device__ ull g_keys[(size_t)BATCH * NPRIOR];

__device__ __forceinline__ unsigned key_from_float(float f) {
    unsigned u = __float_as_uint(f);
    return (u & 0x80000000u) ? ~u : (u | 0x80000000u);
}
__device__ __forceinline__ float float_from_key(unsigned u) {
    return __uint_as_float((u & 0x80000000u) ? (u ^ 0x80000000u) : ~u);
}
__device__ __forceinline__ int bin_of(float m) {
    if (!(m > CONF_TH)) return 0;
    int b = (int)((m - CONF_TH) * BINSCALE);
    if (b > 4094) b = 4094;
    return 1 + b;
}
__device__ __forceinline__ int colclamp(float x) {
    int c = (int)floorf(x * INVCOLW);
    return c < 0 ? 0 : (c > NCOL - 1 ? NCOL - 1 : c);
}
// box = (x1,x2,y1,y2); areas recomputed (w,h>0 so reference clamp is identity)
__device__ __forceinline__ bool pair_sup(float4 a, float4 b, float ab) {
    float xo = fminf(a.y, b.y) - fmaxf(a.x, b.x);
    float yo = fminf(a.w, b.w) - fmaxf(a.z, b.z);
    if (xo > 0.0f && yo > 0.0f) {
        float inter = xo * yo;
        float aa = (a.y - a.x) * (a.w - a.z);
        return inter / (aa + ab - inter + 1e-12f) > NMS_TH;
    }
    return false;
}
__device__ __forceinline__ void prior_of(unsigned idx, float& px, float& py, float& ps) {
    if (idx < 25600u)      { ps = 8.0f;  px = (float)((idx % 160u) * 8u); py = (float)((idx / 160u) * 8u); }
    else if (idx < 32000u) { unsigned j = idx - 25600u; ps = 16.0f; px = (float)((j % 80u) * 16u); py = (float)((j / 80u) * 16u); }
    else                   { unsigned j = idx - 32000u; ps = 32.0f; px = (float)((j % 40u) * 32u); py = (float)((j / 40u) * 32u); }
}

extern __shared__ char smem[];

__global__ __launch_bounds__(1024, 1)
void fused_detector(const float* __restrict__ cls, const float* __restrict__ obj,
                    const float* __restrict__ bbox, const float* __restrict__ kps,
                    float* __restrict__ out, int write_valid) {
    float4* sbox  = (float4*)(smem + OFF_SBOX);
    ull*    skey  = (ull*)   (smem + OFF_SKEY);
    ull*    cand  = (ull*)   (smem + OFF_CAND);
    int*    suf   = (int*)   (smem + OFF_SUF);
    int*    hist  = (int*)   (smem + OFF_HIST);
    float4* colbox= (float4*)(smem + OFF_COLBOX);
    float4* large = (float4*)(smem + OFF_LARGE);
    unsigned short* kpos = (unsigned short*)(smem + OFF_KPOS);
    unsigned char*  keepf= (unsigned char*) (smem + OFF_KEEPF);

    __shared__ int wsum[32];
    __shared__ int sh_cb;
    __shared__ unsigned ovArr[32];
    __shared__ int statArr[32];
    __shared__ int keptCount;
    __shared__ int colcnt[NCOL];
    __shared__ int lcnt;

    const int b = blockIdx.x, tid = threadIdx.x;
    const int lane = tid & 31, warp = tid >> 5;
    const size_t boff = (size_t)b * NPRIOR;

    // ---- P1: init ----
    for (int i = tid; i < NB; i += 1024) hist[i] = 0;
    for (int i = tid; i < TOPK; i += 1024) skey[i] = 0ull;
    if (tid == 0) { sh_cb = 0; keptCount = 0; lcnt = 0; }
    if (tid < NCOL) colcnt[tid] = 0;
    __syncthreads();

    // ---- P2: keys + histogram (keys cached to global scratch) ----
    for (int i = tid; i < NPRIOR; i += 1024) {
        float s = sqrtf(cls[boff + i] * obj[boff + i]);
        float m = (s > CONF_TH) ? s : -1.0f;
        unsigned hk = key_from_float(m);
        g_keys[boff + i] = ((ull)hk << 32) | (unsigned)(~(unsigned)i);
        if (m > CONF_TH) atomicAdd(&hist[bin_of(m)], 1);
    }
    __syncthreads();

    // ---- P3: suffix scan over bins (high->low), cutoff bin ----
    {
        int rbase = tid * 4;
        int v[4];
#pragma unroll
        for (int j = 0; j < 4; j++) v[j] = hist[NB - 1 - (rbase + j)];
        v[1] += v[0]; v[2] += v[1]; v[3] += v[2];
        int tot = v[3];
#pragma unroll
        for (int o = 1; o < 32; o <<= 1) {
            int n = __shfl_up_sync(0xffffffffu, tot, o);
            if (lane >= o) tot += n;
        }
        if (lane == 31) wsum[warp] = tot;
        __syncthreads();
        if (warp == 0) {
            int w = wsum[lane];
#pragma unroll
            for (int o = 1; o < 32; o <<= 1) {
                int n = __shfl_up_sync(0xffffffffu, w, o);
                if (lane >= o) w += n;
            }
            wsum[lane] = w;
        }
        __syncthreads();
        int pre = (warp ? wsum[warp - 1] : 0) + (tot - v[3]);
#pragma unroll
        for (int j = 0; j < 4; j++) suf[NB - 1 - (rbase + j)] = pre + v[j];
        __syncthreads();
        if (tid == 0) { suf[0] = NPRIOR; suf[NB] = 0; }
        __syncthreads();
        int local = -1;
#pragma unroll
        for (int j = 0; j < 4; j++) {
            int bin = NB - 1 - (rbase + j);
            if (bin >= 1 && suf[bin] >= TOPK && bin > local) local = bin;
        }
        if (local >= 0) atomicMax(&sh_cb, local);
        __syncthreads();
    }
    int cb = sh_cb; if (cb < 1) cb = 1;
    int ctot = suf[cb]; if (ctot > CANDS) ctot = CANDS;
    __syncthreads();
    for (int i = tid; i < NB; i += 1024) hist[i] = 0;   // per-bin counters
    __syncthreads();

    // ---- P4: compact candidates (grouped by bin) ----
    for (int i = tid; i < NPRIOR; i += 1024) {
        ull key = g_keys[boff + i];
        float m = float_from_key((unsigned)(key >> 32));
        int bin = bin_of(m);
        if (bin < cb) continue;
        int pos = suf[bin + 1] + atomicAdd(&hist[bin], 1);
        if (pos < CANDS) cand[pos] = key;
    }
    __syncthreads();

    // ---- P5: exact in-bin rank + decode boxes ----
    for (int s = tid; s < ctot; s += 1024) {
        ull key = cand[s];
        float m = float_from_key((unsigned)(key >> 32));
        int bin = bin_of(m);
        int st = suf[bin + 1];
        int en = suf[bin]; if (en > ctot) en = ctot;
        int r = st;
        for (int q = st; q < en; q++)
            if (cand[q] > key) r++;
        if (r >= TOPK) continue;
        skey[r] = key;
        unsigned idx = ~(unsigned)key;
        float px, py, ps; prior_of(idx, px, py, ps);
        const float* bb = bbox + (boff + idx) * 4;
        float cx = px + bb[0] * ps;
        float cy = py + bb[1] * ps;
        float w  = ps * expf(bb[2]);
        float h  = ps * expf(bb[3]);
        float x1 = cx - w * 0.5f, y1 = cy - h * 0.5f;
        sbox[r] = make_float4(x1, x1 + w, y1, y1 + h);
    }
    __syncthreads();   // prep arrays dead -> NMS overlay live

    // ---- P6: greedy NMS, x-binned kept list, early exit at 750 ----
    for (int i = tid; i < TOPK; i += 1024) keepf[i] = 0;
    __syncthreads();

    for (int base = 0; base < TOPK; base += 32) {
        // parallel phase: warp w evaluates candidate base+w
        {
            int p = base + warp;
            bool sup = false;
            float4 bj = make_float4(0.f, 0.f, 0.f, 0.f);
            float aj = 0.f; int stat = 0;
            unsigned ov = 0;
            if (p < TOPK) {
                bj = sbox[p];
                aj = (bj.y - bj.x) * (bj.w - bj.z);
                stat = ((unsigned)(skey[p] >> 32)) > KEYTH;
                // intra-chunk overlaps (earlier lane -> me)
                bool ob = false;
                if (lane < warp) {
                    float4 bi = sbox[base + lane];
                    ob = pair_sup(bi, bj, aj);
                }
                ov = __ballot_sync(0xffffffffu, ob);
                // kept-list scan: only columns my x-interval touches
                int c0 = colclamp(bj.x), c1 = colclamp(bj.y);
                for (int c = c0; c <= c1 && !sup; c++) {
                    int n = colcnt[c];
                    const float4* cp = colbox + c * COLCAP;
                    for (int m = lane; m < n; m += 32) {
                        if (pair_sup(cp[m], bj, aj)) { sup = true; break; }
                    }
                    sup = __any_sync(0xffffffffu, sup);
                }
                if (!sup) {
                    int n = lcnt;
                    for (int m = lane; m < n; m += 32) {
                        if (pair_sup(large[m], bj, aj)) { sup = true; break; }
                    }
                    sup = __any_sync(0xffffffffu, sup);
                }
                if (lane == 0) { ovArr[warp] = ov; statArr[warp] = (stat && !sup) ? 1 : 0; }
            } else if (lane == 0) { ovArr[warp] = 0; statArr[warp] = 0; }
        }
        __syncthreads();

        // resolution phase: warp 0 (fast path + conflicted-only cascade + insert)
        if (warp == 0) {
            unsigned ov = ovArr[lane];
            unsigned alive = __ballot_sync(0xffffffffu, statArr[lane]);
            unsigned conf = __ballot_sync(0xffffffffu,
                                ((alive >> lane) & 1u) && (ov & alive) != 0u);
            unsigned keepmask = alive & ~conf;
            unsigned pend = conf;
            while (pend) {
                int i = __ffs((int)pend) - 1;
                pend &= pend - 1;
                unsigned ovi = __shfl_sync(0xffffffffu, ov, i);
                if ((ovi & keepmask) == 0u) keepmask |= 1u << i;
            }
            int p = base + lane;
            bool mykeep = (keepmask >> lane) & 1u;
            if (p < TOPK) keepf[p] = mykeep ? 1 : 0;
            int off = __popc(keepmask & ((1u << lane) - 1u));
            int b0 = keptCount;
            if (mykeep) {
                kpos[b0 + off] = (unsigned short)p;
                float4 bl = sbox[p];
                int c0 = colclamp(bl.x), c1 = colclamp(bl.y);
                if (c1 - c0 >= 3) {                     // wide box -> large list
                    int d = atomicAdd(&lcnt, 1);
                    if (d < LARGECAP) large[d] = bl;
                } else {
                    for (int c = c0; c <= c1; c++) {
                        int d = atomicAdd(&colcnt[c], 1);
                        if (d < COLCAP) colbox[c * COLCAP + d] = bl;
                        else { int e = atomicAdd(&lcnt, 1); if (e < LARGECAP) large[e] = bl; }
                    }
                }
            }
            if (lane == 0) keptCount = b0 + __popc(keepmask);
        }
        __syncthreads();
        if (keptCount >= KEEPK) break;
    }
    __syncthreads();

    int kc = keptCount;
    int kout = kc < KEEPK ? kc : KEEPK;

    // ---- parallel filler: first (KEEPK-kc) non-kept positions in order ----
    if (kc < KEEPK) {
        int need = KEEPK - kc;
        int j0 = tid * 5;
        int cnt = 0;
#pragma unroll
        for (int j = 0; j < 5; j++) {
            int p = j0 + j;
            if (p < TOPK && !keepf[p]) cnt++;
        }
        int x = cnt;
#pragma unroll
        for (int o = 1; o < 32; o <<= 1) {
            int n = __shfl_up_sync(0xffffffffu, x, o);
            if (lane >= o) x += n;
        }
        if (lane == 31) wsum[warp] = x;
        __syncthreads();
        if (warp == 0) {
            int w = wsum[lane];
#pragma unroll
            for (int o = 1; o < 32; o <<= 1) {
                int n = __shfl_up_sync(0xffffffffu, w, o);
                if (lane >= o) w += n;
            }
            wsum[lane] = w;
        }
        __syncthreads();
        int pre = (warp ? wsum[warp - 1] : 0) + (x - cnt);
#pragma unroll
        for (int j = 0; j < 5; j++) {
            int p = j0 + j;
            if (p < TOPK && !keepf[p]) {
                if (pre < need) kpos[kc + pre] = (unsigned short)p;
                pre++;
            }
        }
    }
    __syncthreads();

    // ---- P7: write final 750 rows ----
    for (int r = tid; r < KEEPK; r += 1024) {
        int pos = kpos[r];
        ull key = skey[pos];
        unsigned idx = ~(unsigned)key;
        float score = float_from_key((unsigned)(key >> 32));
        float px, py, ps; prior_of(idx, px, py, ps);
        const float* bb = bbox + (boff + idx) * 4;
        float cx = px + bb[0] * ps, cy = py + bb[1] * ps;
        float w = ps * expf(bb[2]), h = ps * expf(bb[3]);
        float x1 = cx - w * 0.5f, y1 = cy - h * 0.5f;
        size_t t = (size_t)b * KEEPK + r;
        float* o = out + t * 15;
        o[0] = x1; o[1] = y1; o[2] = x1 + w; o[3] = y1 + h;
        const float* kp = kps + (boff + idx) * 10;
#pragma unroll
        for (int m = 0; m < 5; m++) {
            o[4 + 2 * m] = px + kp[2 * m] * ps;
            o[5 + 2 * m] = py + kp[2 * m + 1] * ps;
        }
        o[14] = score;
        if (write_valid)
            out[(size_t)BATCH * KEEPK * 15 + t] = (r < kout) ? 1.0f : 0.0f;
    }
}

extern "C" void kernel_launch(void* const* d_in, const int* in_sizes, int n_in,
                              void* d_out, int out_size) {
    const float* cls  = (const float*)d_in[0];
    const float* obj  = (const float*)d_in[1];
    const float* bbox = (const float*)d_in[2];
    const float* kps  = (const float*)d_in[3];
    float* out = (float*)d_out;

    static int attr_set = 0;
    if (!attr_set) {
        cudaFuncSetAttribute(fused_detector, cudaFuncAttributeMaxDynamicSharedMemorySize,
                             SMEM_TOTAL);
        attr_set = 1;
    }
    int write_valid = (out_size >= BATCH * KEEPK * 16) ? 1 : 0;
    fused_detector<<<BATCH, 1024, SMEM_TOTAL>>>(cls, obj, bbox, kps, out, write_valid);
}